// round 4
// baseline (speedup 1.0000x reference)
#include <cuda_runtime.h>
#include <cuda_bf16.h>
#include <math.h>

// Problem constants
#define LAYERS 6
#define Hc 1024
#define NHc 16
#define Dc 64
#define Fc 4096
#define Bc 4
#define Sc 512
#define Mrows (Bc * Sc)          // 2048
#define LN_EPS 1e-12f
#define GELU_C 0.7978845608028654f

// ---------------------------------------------------------------------------
// Scratch buffers (device globals; no allocation allowed)
// ---------------------------------------------------------------------------
__device__ float g_h[Mrows * Hc];
__device__ float g_q[Mrows * Hc];
__device__ float g_k[Mrows * Hc];
__device__ float g_v[Mrows * Hc];
__device__ float g_a[Mrows * Hc];
__device__ float g_t[Mrows * Hc];
__device__ float g_x1[Mrows * Hc];
__device__ float g_x2[Mrows * Hc];
__device__ float g_x3[Mrows * Hc];
__device__ float g_inter[Mrows * Fc];

// ---------------------------------------------------------------------------
// GEMM: C[M,N] = A[M,K] @ W[K,N] + bias[N] (+ add[M,N]) (+ gelu)
// 64x64 block tile, BK=16, 256 threads, 4x4 per thread.
// Assumes M%64==0, N%64==0, K%16==0 (true for all calls here).
// ---------------------------------------------------------------------------
#define BM 64
#define BN 64
#define BK 16

__device__ __forceinline__ float gelu_new(float x) {
    return 0.5f * x * (1.0f + tanhf(GELU_C * (x + 0.044715f * x * x * x)));
}

__global__ __launch_bounds__(256) void gemm_kernel(
    const float* __restrict__ A, const float* __restrict__ W,
    const float* __restrict__ bias, const float* __restrict__ add,
    float* __restrict__ C, int M, int N, int K, int fuse_gelu)
{
    __shared__ float As[BM][BK + 1];
    __shared__ float Bs[BK][BN + 1];

    const int tid = threadIdx.x;
    const int bm = blockIdx.y * BM;
    const int bn = blockIdx.x * BN;
    const int tx = tid & 15;
    const int ty = tid >> 4;

    float acc[4][4] = {};

    for (int k0 = 0; k0 < K; k0 += BK) {
        // Load A tile: 64x16 = 1024 elems, 4 per thread
        #pragma unroll
        for (int l = 0; l < 4; l++) {
            int e = tid + 256 * l;
            int m = e >> 4, k = e & 15;
            As[m][k] = A[(bm + m) * K + k0 + k];
        }
        // Load W tile: 16x64
        #pragma unroll
        for (int l = 0; l < 4; l++) {
            int e = tid + 256 * l;
            int k = e >> 6, n = e & 63;
            Bs[k][n] = W[(k0 + k) * N + bn + n];
        }
        __syncthreads();

        #pragma unroll
        for (int k = 0; k < BK; k++) {
            float a[4], b[4];
            #pragma unroll
            for (int i = 0; i < 4; i++) a[i] = As[ty * 4 + i][k];
            #pragma unroll
            for (int j = 0; j < 4; j++) b[j] = Bs[k][tx * 4 + j];
            #pragma unroll
            for (int i = 0; i < 4; i++)
                #pragma unroll
                for (int j = 0; j < 4; j++)
                    acc[i][j] += a[i] * b[j];
        }
        __syncthreads();
    }

    #pragma unroll
    for (int i = 0; i < 4; i++) {
        int row = bm + ty * 4 + i;
        #pragma unroll
        for (int j = 0; j < 4; j++) {
            int col = bn + tx * 4 + j;
            float val = acc[i][j] + bias[col];
            if (add) val += add[row * N + col];
            if (fuse_gelu) val = gelu_new(val);
            C[row * N + col] = val;
        }
    }
}

// ---------------------------------------------------------------------------
// Attention: out = softmax(Q K^T * scale + maskadd) V  for all heads.
// Q,K,V are [B, S, H] with heads interleaved (h = n*D + d).
// One block handles QT=8 query rows for one (b, head). 256 threads.
// ---------------------------------------------------------------------------
#define QT 8

__global__ __launch_bounds__(256) void attn_kernel(
    const float* __restrict__ Q, const float* __restrict__ Kk,
    const float* __restrict__ V, const int* __restrict__ mask,
    float* __restrict__ O, int Sq, int Skv)
{
    __shared__ float qs[QT][Dc];
    __shared__ float p[QT][Sc];   // Skv <= Sc

    const int tid = threadIdx.x;
    const int nqt = Sq / QT;
    const int qt = blockIdx.x % nqt;
    const int n  = (blockIdx.x / nqt) % NHc;
    const int b  = blockIdx.x / (nqt * NHc);
    const int i0 = qt * QT;

    // Load Q tile [QT][D]
    for (int e = tid; e < QT * Dc; e += 256) {
        int r = e / Dc, d = e % Dc;
        qs[r][d] = Q[(b * Sq + i0 + r) * Hc + n * Dc + d];
    }
    __syncthreads();

    // Scores: each thread owns key columns j = tid, tid+256
    for (int j = tid; j < Skv; j += 256) {
        const float* kp = Kk + (b * Skv + j) * Hc + n * Dc;
        float acc[QT];
        #pragma unroll
        for (int r = 0; r < QT; r++) acc[r] = 0.f;
        #pragma unroll 16
        for (int d = 0; d < Dc; d++) {
            float kd = kp[d];
            #pragma unroll
            for (int r = 0; r < QT; r++) acc[r] += qs[r][d] * kd;
        }
        float madd = mask[b * Skv + j] ? 0.f : -10000.f;
        #pragma unroll
        for (int r = 0; r < QT; r++) p[r][j] = acc[r] * 0.125f + madd;
    }
    __syncthreads();

    // Softmax: warp w handles row w (8 warps, 8 rows)
    {
        int w = tid >> 5, lane = tid & 31;
        float m = -1e30f;
        for (int j = lane; j < Skv; j += 32) m = fmaxf(m, p[w][j]);
        #pragma unroll
        for (int o = 16; o > 0; o >>= 1) m = fmaxf(m, __shfl_xor_sync(0xffffffffu, m, o));
        float s = 0.f;
        for (int j = lane; j < Skv; j += 32) {
            float e = __expf(p[w][j] - m);
            p[w][j] = e;
            s += e;
        }
        #pragma unroll
        for (int o = 16; o > 0; o >>= 1) s += __shfl_xor_sync(0xffffffffu, s, o);
        float inv = 1.f / s;
        for (int j = lane; j < Skv; j += 32) p[w][j] *= inv;
    }
    __syncthreads();

    // Output: group g = tid/64 handles rows {2g, 2g+1}, lane dim d = tid%64
    const int d = tid & 63;
    const int r0 = (tid >> 6) * 2;
    float a0 = 0.f, a1 = 0.f;
    for (int j = 0; j < Skv; j++) {
        float vd = V[(b * Skv + j) * Hc + n * Dc + d];
        a0 += p[r0][j] * vd;
        a1 += p[r0 + 1][j] * vd;
    }
    O[(b * Sq + i0 + r0) * Hc + n * Dc + d]     = a0;
    O[(b * Sq + i0 + r0 + 1) * Hc + n * Dc + d] = a1;
}

// ---------------------------------------------------------------------------
// LayerNorm over H=1024: one block (256 threads) per row.
// ln points at [2, H]: gamma = ln[0:H], beta = ln[H:2H].
// ---------------------------------------------------------------------------
__device__ __forceinline__ float block_sum_256(float v) {
    __shared__ float sh[8];
    #pragma unroll
    for (int o = 16; o > 0; o >>= 1) v += __shfl_xor_sync(0xffffffffu, v, o);
    __syncthreads();
    if ((threadIdx.x & 31) == 0) sh[threadIdx.x >> 5] = v;
    __syncthreads();
    float t = sh[0];
    #pragma unroll
    for (int i = 1; i < 8; i++) t += sh[i];
    return t;
}

__global__ __launch_bounds__(256) void ln_kernel(
    const float* __restrict__ x, const float* __restrict__ ln,
    float* __restrict__ out)
{
    const int row = blockIdx.x, tid = threadIdx.x;
    const float* xr = x + row * Hc;
    float v[4];
    float s = 0.f;
    #pragma unroll
    for (int i = 0; i < 4; i++) { v[i] = xr[tid + 256 * i]; s += v[i]; }
    s = block_sum_256(s);
    const float mean = s * (1.f / Hc);
    float q = 0.f;
    #pragma unroll
    for (int i = 0; i < 4; i++) { float d = v[i] - mean; q += d * d; }
    q = block_sum_256(q);
    const float inv = rsqrtf(q * (1.f / Hc) + LN_EPS);
    #pragma unroll
    for (int i = 0; i < 4; i++) {
        int c = tid + 256 * i;
        out[row * Hc + c] = (v[i] - mean) * inv * ln[c] + ln[Hc + c];
    }
}

// ---------------------------------------------------------------------------
// Orchestration
// ---------------------------------------------------------------------------
extern "C" void kernel_launch(void* const* d_in, const int* in_sizes, int n_in,
                              void* d_out, int out_size)
{
    const float* hidden   = (const float*)d_in[0];
    const float* enc      = (const float*)d_in[1];
    const int*   amask    = (const int*)d_in[2];
    const int*   emask    = (const int*)d_in[3];
    const float* sa_qkv_w = (const float*)d_in[4];
    const float* sa_qkv_b = (const float*)d_in[5];
    const float* sa_out_w = (const float*)d_in[6];
    const float* sa_out_b = (const float*)d_in[7];
    const float* sa_ln    = (const float*)d_in[8];
    const float* ca_qkv_w = (const float*)d_in[9];
    const float* ca_qkv_b = (const float*)d_in[10];
    const float* ca_out_w = (const float*)d_in[11];
    const float* ca_out_b = (const float*)d_in[12];
    const float* ca_ln    = (const float*)d_in[13];
    const float* o1_w     = (const float*)d_in[14];
    const float* o1_b     = (const float*)d_in[15];
    const float* o1_ln    = (const float*)d_in[16];
    const float* ffn_w    = (const float*)d_in[17];
    const float* ffn_b    = (const float*)d_in[18];
    const float* o2_w     = (const float*)d_in[19];
    const float* o2_b     = (const float*)d_in[20];
    const float* o2_ln    = (const float*)d_in[21];
    float* out = (float*)d_out;

    float *h, *q, *k, *v, *a, *t, *x1, *x2, *x3, *inter;
    cudaGetSymbolAddress((void**)&h,  g_h);
    cudaGetSymbolAddress((void**)&q,  g_q);
    cudaGetSymbolAddress((void**)&k,  g_k);
    cudaGetSymbolAddress((void**)&v,  g_v);
    cudaGetSymbolAddress((void**)&a,  g_a);
    cudaGetSymbolAddress((void**)&t,  g_t);
    cudaGetSymbolAddress((void**)&x1, g_x1);
    cudaGetSymbolAddress((void**)&x2, g_x2);
    cudaGetSymbolAddress((void**)&x3, g_x3);
    cudaGetSymbolAddress((void**)&inter, g_inter);

    cudaMemcpyAsync(h, hidden, (size_t)Mrows * Hc * sizeof(float),
                    cudaMemcpyDeviceToDevice, 0);

    const dim3 g1(Hc / BN, Mrows / BM);    // N=1024 GEMMs
    const dim3 gF(Fc / BN, Mrows / BM);    // N=4096 GEMM
    const int attnBlocks = Bc * NHc * (Sc / QT);   // 4096

    for (int i = 0; i < LAYERS; i++) {
        // ---- self attention ----
        const float* W  = sa_qkv_w + (size_t)i * 3 * Hc * Hc;
        const float* Bb = sa_qkv_b + (size_t)i * 3 * Hc;
        gemm_kernel<<<g1, 256>>>(h, W,                 Bb,          nullptr, q, Mrows, Hc, Hc, 0);
        gemm_kernel<<<g1, 256>>>(h, W + Hc * Hc,       Bb + Hc,     nullptr, k, Mrows, Hc, Hc, 0);
        gemm_kernel<<<g1, 256>>>(h, W + 2 * Hc * Hc,   Bb + 2 * Hc, nullptr, v, Mrows, Hc, Hc, 0);
        attn_kernel<<<attnBlocks, 256>>>(q, k, v, amask, a, Sc, Sc);
        gemm_kernel<<<g1, 256>>>(a, sa_out_w + (size_t)i * Hc * Hc, sa_out_b + i * Hc, h, t,
                                 Mrows, Hc, Hc, 0);
        ln_kernel<<<Mrows, 256>>>(t, sa_ln + (size_t)i * 2 * Hc, x1);

        // ---- cross attention (queries from h, keys/values from encoder) ----
        const float* Wc  = ca_qkv_w + (size_t)i * 3 * Hc * Hc;
        const float* Bbc = ca_qkv_b + (size_t)i * 3 * Hc;
        gemm_kernel<<<g1, 256>>>(h,   Wc,               Bbc,          nullptr, q, Mrows, Hc, Hc, 0);
        gemm_kernel<<<g1, 256>>>(enc, Wc + Hc * Hc,     Bbc + Hc,     nullptr, k, Mrows, Hc, Hc, 0);
        gemm_kernel<<<g1, 256>>>(enc, Wc + 2 * Hc * Hc, Bbc + 2 * Hc, nullptr, v, Mrows, Hc, Hc, 0);
        attn_kernel<<<attnBlocks, 256>>>(q, k, v, emask, a, Sc, Sc);
        gemm_kernel<<<g1, 256>>>(a, ca_out_w + (size_t)i * Hc * Hc, ca_out_b + i * Hc, h, t,
                                 Mrows, Hc, Hc, 0);
        ln_kernel<<<Mrows, 256>>>(t, ca_ln + (size_t)i * 2 * Hc, x2);

        // ---- output_1: x3 = LN(x1 @ o1_w + b + x2) ----
        gemm_kernel<<<g1, 256>>>(x1, o1_w + (size_t)i * Hc * Hc, o1_b + i * Hc, x2, t,
                                 Mrows, Hc, Hc, 0);
        ln_kernel<<<Mrows, 256>>>(t, o1_ln + (size_t)i * 2 * Hc, x3);

        // ---- FFN: inter = gelu(x3 @ ffn_w + b); h = LN(inter @ o2_w + b + x3) ----
        gemm_kernel<<<gF, 256>>>(x3, ffn_w + (size_t)i * Hc * Fc, ffn_b + (size_t)i * Fc,
                                 nullptr, inter, Mrows, Fc, Hc, 1);
        gemm_kernel<<<g1, 256>>>(inter, o2_w + (size_t)i * Fc * Hc, o2_b + i * Hc, x3, t,
                                 Mrows, Hc, Fc, 0);
        ln_kernel<<<Mrows, 256>>>(t, o2_ln + (size_t)i * 2 * Hc,
                                  (i == LAYERS - 1) ? out : h);
    }
}

// round 7
// speedup vs baseline: 2.4218x; 2.4218x over previous
#include <cuda_runtime.h>
#include <math.h>

#define LAYERS 6
#define Hc 1024
#define NHc 16
#define Dc 64
#define Fc 4096
#define Bc 4
#define Sc 512
#define Mrows (Bc * Sc)
#define LN_EPS 1e-12f
#define GELU_C 0.7978845608028654f

__device__ float g_h[Mrows * Hc];
__device__ float g_q[Mrows * Hc];
__device__ float g_k[Mrows * Hc];
__device__ float g_v[Mrows * Hc];
__device__ float g_a[Mrows * Hc];
__device__ float g_t[Mrows * Hc];
__device__ float g_x1[Mrows * Hc];
__device__ float g_x2[Mrows * Hc];
__device__ float g_x3[Mrows * Hc];
__device__ float g_inter[Mrows * Fc];

// ---- TF32 hi/lo split helpers ----
__device__ __forceinline__ unsigned f2tf32(float x) {
    unsigned r;
    asm("cvt.rna.tf32.f32 %0, %1;" : "=r"(r) : "f"(x));
    return r;
}
__device__ __forceinline__ void tfsplit(float x, unsigned& h, unsigned& l) {
    h = f2tf32(x);
    l = f2tf32(x - __uint_as_float(h));
}
__device__ __forceinline__ void mma8(float* c, const unsigned* a, const unsigned* b) {
    asm("mma.sync.aligned.m16n8k8.row.col.f32.tf32.tf32.f32 "
        "{%0,%1,%2,%3}, {%4,%5,%6,%7}, {%8,%9}, {%0,%1,%2,%3};"
        : "+f"(c[0]), "+f"(c[1]), "+f"(c[2]), "+f"(c[3])
        : "r"(a[0]), "r"(a[1]), "r"(a[2]), "r"(a[3]), "r"(b[0]), "r"(b[1]));
}
__device__ __forceinline__ float gelu_new(float x) {
    return 0.5f * x * (1.0f + tanhf(GELU_C * (x + 0.044715f * x * x * x)));
}

// ---------------------------------------------------------------------------
// GEMM (tf32x2): C[M,N] = A@W + bias (+add) (+gelu). 128x128x16 tiles,
// 256 threads = 8 warps (2x4), 64x32 warp tile, double-buffered smem.
// ---------------------------------------------------------------------------
#define GBM 128
#define GBN 128
#define GBK 16
#define LDA 136
#define LDB 136
#define GEMM_SMEM (4 * 2 * GBK * LDA * 4)

__global__ __launch_bounds__(256) void gemm_tc(
    const float* __restrict__ A, const float* __restrict__ W,
    const float* __restrict__ bias, const float* __restrict__ add,
    float* __restrict__ C, int M, int N, int K, int fuse_gelu)
{
    extern __shared__ unsigned sm_g[];
    unsigned* Ah = sm_g;
    unsigned* Al = Ah + 2 * GBK * LDA;
    unsigned* Bh = Al + 2 * GBK * LDA;
    unsigned* Bl = Bh + 2 * GBK * LDB;

    const int tid = threadIdx.x, lane = tid & 31, warp = tid >> 5;
    const int wr = warp >> 2, wc = warp & 3;
    const int g = lane >> 2, tg = lane & 3;
    const int bm = blockIdx.y * GBM, bn = blockIdx.x * GBN;
    const int am = tid >> 1, ak = (tid & 1) * 8;
    const int bk = tid >> 4, bnn = (tid & 15) * 8;

    float acc[4][4][4];
    #pragma unroll
    for (int i = 0; i < 4; i++)
        #pragma unroll
        for (int j = 0; j < 4; j++)
            #pragma unroll
            for (int r = 0; r < 4; r++) acc[i][j][r] = 0.f;

    float ar[8], br[8];
    const float* Abase = A + (size_t)(bm + am) * K + ak;
    const float* Wbase = W + (size_t)bk * N + bn + bnn;

    auto loadT = [&](int t) {
        const float4* pa = (const float4*)(Abase + t * GBK);
        float4 u = pa[0], v2 = pa[1];
        ar[0] = u.x; ar[1] = u.y; ar[2] = u.z; ar[3] = u.w;
        ar[4] = v2.x; ar[5] = v2.y; ar[6] = v2.z; ar[7] = v2.w;
        const float4* pb = (const float4*)(Wbase + (size_t)t * GBK * N);
        float4 x = pb[0], y = pb[1];
        br[0] = x.x; br[1] = x.y; br[2] = x.z; br[3] = x.w;
        br[4] = y.x; br[5] = y.y; br[6] = y.z; br[7] = y.w;
    };
    auto storeT = [&](int buf) {
        #pragma unroll
        for (int i = 0; i < 8; i++) {
            unsigned h, l; tfsplit(ar[i], h, l);
            Ah[(buf * GBK + ak + i) * LDA + am] = h;
            Al[(buf * GBK + ak + i) * LDA + am] = l;
        }
        unsigned bh8[8], bl8[8];
        #pragma unroll
        for (int i = 0; i < 8; i++) tfsplit(br[i], bh8[i], bl8[i]);
        uint4* ph = (uint4*)&Bh[(buf * GBK + bk) * LDB + bnn];
        ph[0] = make_uint4(bh8[0], bh8[1], bh8[2], bh8[3]);
        ph[1] = make_uint4(bh8[4], bh8[5], bh8[6], bh8[7]);
        uint4* pl = (uint4*)&Bl[(buf * GBK + bk) * LDB + bnn];
        pl[0] = make_uint4(bl8[0], bl8[1], bl8[2], bl8[3]);
        pl[1] = make_uint4(bl8[4], bl8[5], bl8[6], bl8[7]);
    };
    auto compute = [&](int buf) {
        #pragma unroll
        for (int kk = 0; kk < GBK; kk += 8) {
            const int r0 = (buf * GBK + kk + tg) * LDA;
            const int r1 = (buf * GBK + kk + tg + 4) * LDA;
            unsigned ah[4][4], al_[4][4];
            #pragma unroll
            for (int i = 0; i < 4; i++) {
                int rb = wr * 64 + i * 16 + g;
                ah[i][0] = Ah[r0 + rb];   ah[i][1] = Ah[r0 + rb + 8];
                ah[i][2] = Ah[r1 + rb];   ah[i][3] = Ah[r1 + rb + 8];
                al_[i][0] = Al[r0 + rb];  al_[i][1] = Al[r0 + rb + 8];
                al_[i][2] = Al[r1 + rb];  al_[i][3] = Al[r1 + rb + 8];
            }
            const int s0 = (buf * GBK + kk + tg) * LDB;
            const int s1 = (buf * GBK + kk + tg + 4) * LDB;
            #pragma unroll
            for (int j = 0; j < 4; j++) {
                int cb = wc * 32 + j * 8 + g;
                unsigned bh2[2], bl2[2];
                bh2[0] = Bh[s0 + cb]; bh2[1] = Bh[s1 + cb];
                bl2[0] = Bl[s0 + cb]; bl2[1] = Bl[s1 + cb];
                #pragma unroll
                for (int i = 0; i < 4; i++) {
                    mma8(acc[i][j], ah[i], bh2);
                    mma8(acc[i][j], ah[i], bl2);
                    mma8(acc[i][j], al_[i], bh2);
                }
            }
        }
    };

    const int T = K / GBK;
    loadT(0); storeT(0); __syncthreads();
    for (int t = 0; t < T; t++) {
        int cur = t & 1;
        if (t + 1 < T) loadT(t + 1);
        compute(cur);
        if (t + 1 < T) storeT(cur ^ 1);
        __syncthreads();
    }

    #pragma unroll
    for (int i = 0; i < 4; i++) {
        int row0 = bm + wr * 64 + i * 16 + g;
        #pragma unroll
        for (int j = 0; j < 4; j++) {
            int col = bn + wc * 32 + j * 8 + 2 * tg;
            float2 bz = *(const float2*)(bias + col);
            float v0 = acc[i][j][0] + bz.x, v1 = acc[i][j][1] + bz.y;
            float v2 = acc[i][j][2] + bz.x, v3 = acc[i][j][3] + bz.y;
            if (add) {
                float2 a0 = *(const float2*)(add + (size_t)row0 * N + col);
                float2 a1 = *(const float2*)(add + (size_t)(row0 + 8) * N + col);
                v0 += a0.x; v1 += a0.y; v2 += a1.x; v3 += a1.y;
            }
            if (fuse_gelu) {
                v0 = gelu_new(v0); v1 = gelu_new(v1);
                v2 = gelu_new(v2); v3 = gelu_new(v3);
            }
            *(float2*)(C + (size_t)row0 * N + col) = make_float2(v0, v1);
            *(float2*)(C + (size_t)(row0 + 8) * N + col) = make_float2(v2, v3);
        }
    }
}

// ---------------------------------------------------------------------------
// FlashAttention (tf32x2). Block = 128 q rows of one (b,head); 8 warps x 16
// rows; kv tiles of 64; online softmax; P acc->A frag via shuffles.
// ---------------------------------------------------------------------------
#define LDQ 68
#define LDK 68
#define LDV 72
#define ATTN_SMEM ((2 * 128 * LDQ + 2 * 64 * LDK + 2 * 64 * LDV) * 4 + Sc * 4)

__global__ __launch_bounds__(256) void attn_tc(
    const float* __restrict__ Q, const float* __restrict__ Kin,
    const float* __restrict__ Vin, const int* __restrict__ mask,
    float* __restrict__ O)
{
    extern __shared__ unsigned sm_a[];
    unsigned* Qh = sm_a;
    unsigned* Ql = Qh + 128 * LDQ;
    unsigned* Kh = Ql + 128 * LDQ;
    unsigned* Kl = Kh + 64 * LDK;
    unsigned* Vh = Kl + 64 * LDK;
    unsigned* Vl = Vh + 64 * LDV;
    float* madd = (float*)(Vl + 64 * LDV);

    const int tid = threadIdx.x, lane = tid & 31, warp = tid >> 5;
    const int g = lane >> 2, tg = lane & 3;
    const int qt = blockIdx.x & 3;
    const int n  = (blockIdx.x >> 2) & 15;
    const int b  = blockIdx.x >> 6;

    for (int j = tid; j < Sc; j += 256)
        madd[j] = mask[b * Sc + j] ? 0.f : -10000.f;

    {
        int r = tid >> 1, d0 = (tid & 1) * 32;
        const float* qp = Q + (size_t)(b * Sc + qt * 128 + r) * Hc + n * Dc + d0;
        #pragma unroll
        for (int i = 0; i < 32; i += 4) {
            float4 v = *(const float4*)(qp + i);
            unsigned h0, l0, h1, l1, h2, l2, h3, l3;
            tfsplit(v.x, h0, l0); tfsplit(v.y, h1, l1);
            tfsplit(v.z, h2, l2); tfsplit(v.w, h3, l3);
            *(uint4*)&Qh[r * LDQ + d0 + i] = make_uint4(h0, h1, h2, h3);
            *(uint4*)&Ql[r * LDQ + d0 + i] = make_uint4(l0, l1, l2, l3);
        }
    }
    __syncthreads();

    float o[8][4];
    #pragma unroll
    for (int j = 0; j < 8; j++)
        #pragma unroll
        for (int r = 0; r < 4; r++) o[j][r] = 0.f;
    float m_run[2] = {-1e30f, -1e30f};
    float l_run[2] = {0.f, 0.f};

    for (int kv = 0; kv < Sc; kv += 64) {
        {
            int r = tid >> 2, d0 = (tid & 3) * 16;
            const float* kp = Kin + (size_t)(b * Sc + kv + r) * Hc + n * Dc + d0;
            const float* vp = Vin + (size_t)(b * Sc + kv + r) * Hc + n * Dc + d0;
            #pragma unroll
            for (int i = 0; i < 16; i += 4) {
                float4 kd = *(const float4*)(kp + i);
                unsigned h0, l0, h1, l1, h2, l2, h3, l3;
                tfsplit(kd.x, h0, l0); tfsplit(kd.y, h1, l1);
                tfsplit(kd.z, h2, l2); tfsplit(kd.w, h3, l3);
                *(uint4*)&Kh[r * LDK + d0 + i] = make_uint4(h0, h1, h2, h3);
                *(uint4*)&Kl[r * LDK + d0 + i] = make_uint4(l0, l1, l2, l3);
                float4 vd = *(const float4*)(vp + i);
                tfsplit(vd.x, h0, l0); tfsplit(vd.y, h1, l1);
                tfsplit(vd.z, h2, l2); tfsplit(vd.w, h3, l3);
                *(uint4*)&Vh[r * LDV + d0 + i] = make_uint4(h0, h1, h2, h3);
                *(uint4*)&Vl[r * LDV + d0 + i] = make_uint4(l0, l1, l2, l3);
            }
        }
        __syncthreads();

        float s[8][4];
        #pragma unroll
        for (int j = 0; j < 8; j++)
            #pragma unroll
            for (int r = 0; r < 4; r++) s[j][r] = 0.f;
        #pragma unroll
        for (int kk = 0; kk < 64; kk += 8) {
            unsigned qh[4], ql_[4];
            int rb = warp * 16 + g;
            qh[0] = Qh[rb * LDQ + kk + tg];       qh[1] = Qh[(rb + 8) * LDQ + kk + tg];
            qh[2] = Qh[rb * LDQ + kk + tg + 4];   qh[3] = Qh[(rb + 8) * LDQ + kk + tg + 4];
            ql_[0] = Ql[rb * LDQ + kk + tg];      ql_[1] = Ql[(rb + 8) * LDQ + kk + tg];
            ql_[2] = Ql[rb * LDQ + kk + tg + 4];  ql_[3] = Ql[(rb + 8) * LDQ + kk + tg + 4];
            #pragma unroll
            for (int j = 0; j < 8; j++) {
                unsigned kh2[2], kl2[2];
                kh2[0] = Kh[(j * 8 + g) * LDK + kk + tg];
                kh2[1] = Kh[(j * 8 + g) * LDK + kk + tg + 4];
                kl2[0] = Kl[(j * 8 + g) * LDK + kk + tg];
                kl2[1] = Kl[(j * 8 + g) * LDK + kk + tg + 4];
                mma8(s[j], qh, kh2);
                mma8(s[j], qh, kl2);
                mma8(s[j], ql_, kh2);
            }
        }

        float corr[2];
        #pragma unroll
        for (int r2 = 0; r2 < 2; r2++) {
            float mx = m_run[r2];
            #pragma unroll
            for (int j = 0; j < 8; j++)
                #pragma unroll
                for (int c = 0; c < 2; c++) {
                    float val = s[j][r2 * 2 + c] * 0.125f + madd[kv + j * 8 + 2 * tg + c];
                    s[j][r2 * 2 + c] = val;
                    mx = fmaxf(mx, val);
                }
            mx = fmaxf(mx, __shfl_xor_sync(0xffffffffu, mx, 1));
            mx = fmaxf(mx, __shfl_xor_sync(0xffffffffu, mx, 2));
            corr[r2] = __expf(m_run[r2] - mx);
            m_run[r2] = mx;
            float rs = 0.f;
            #pragma unroll
            for (int j = 0; j < 8; j++)
                #pragma unroll
                for (int c = 0; c < 2; c++) {
                    float e = __expf(s[j][r2 * 2 + c] - mx);
                    s[j][r2 * 2 + c] = e;
                    rs += e;
                }
            rs += __shfl_xor_sync(0xffffffffu, rs, 1);
            rs += __shfl_xor_sync(0xffffffffu, rs, 2);
            l_run[r2] = l_run[r2] * corr[r2] + rs;
        }
        #pragma unroll
        for (int j = 0; j < 8; j++) {
            o[j][0] *= corr[0]; o[j][1] *= corr[0];
            o[j][2] *= corr[1]; o[j][3] *= corr[1];
        }

        #pragma unroll
        for (int kf = 0; kf < 8; kf++) {
            int src0 = (g << 2) | (tg >> 1);
            int src1 = src0 + 2;
            float v0 = __shfl_sync(0xffffffffu, s[kf][0], src0);
            float v1 = __shfl_sync(0xffffffffu, s[kf][1], src0);
            float v2 = __shfl_sync(0xffffffffu, s[kf][2], src0);
            float v3 = __shfl_sync(0xffffffffu, s[kf][3], src0);
            float w0 = __shfl_sync(0xffffffffu, s[kf][0], src1);
            float w1 = __shfl_sync(0xffffffffu, s[kf][1], src1);
            float w2 = __shfl_sync(0xffffffffu, s[kf][2], src1);
            float w3 = __shfl_sync(0xffffffffu, s[kf][3], src1);
            float p0 = (tg & 1) ? v1 : v0;
            float p1 = (tg & 1) ? v3 : v2;
            float p2 = (tg & 1) ? w1 : w0;
            float p3 = (tg & 1) ? w3 : w2;
            unsigned ph[4], pl[4];
            tfsplit(p0, ph[0], pl[0]); tfsplit(p1, ph[1], pl[1]);
            tfsplit(p2, ph[2], pl[2]); tfsplit(p3, ph[3], pl[3]);
            #pragma unroll
            for (int j = 0; j < 8; j++) {
                unsigned vh2[2], vl2[2];
                vh2[0] = Vh[(kf * 8 + tg) * LDV + j * 8 + g];
                vh2[1] = Vh[(kf * 8 + tg + 4) * LDV + j * 8 + g];
                vl2[0] = Vl[(kf * 8 + tg) * LDV + j * 8 + g];
                vl2[1] = Vl[(kf * 8 + tg + 4) * LDV + j * 8 + g];
                mma8(o[j], ph, vh2);
                mma8(o[j], ph, vl2);
                mma8(o[j], pl, vh2);
            }
        }
        __syncthreads();
    }

    float inv0 = 1.f / l_run[0], inv1 = 1.f / l_run[1];
    int row0 = b * Sc + qt * 128 + warp * 16 + g;
    #pragma unroll
    for (int j = 0; j < 8; j++) {
        int col = n * Dc + j * 8 + 2 * tg;
        *(float2*)(O + (size_t)row0 * Hc + col) =
            make_float2(o[j][0] * inv0, o[j][1] * inv0);
        *(float2*)(O + (size_t)(row0 + 8) * Hc + col) =
            make_float2(o[j][2] * inv1, o[j][3] * inv1);
    }
}

// ---------------------------------------------------------------------------
// LayerNorm over H=1024
// ---------------------------------------------------------------------------
__device__ __forceinline__ float block_sum_256(float v) {
    __shared__ float sh[8];
    #pragma unroll
    for (int o = 16; o > 0; o >>= 1) v += __shfl_xor_sync(0xffffffffu, v, o);
    __syncthreads();
    if ((threadIdx.x & 31) == 0) sh[threadIdx.x >> 5] = v;
    __syncthreads();
    float t = sh[0];
    #pragma unroll
    for (int i = 1; i < 8; i++) t += sh[i];
    return t;
}

__global__ __launch_bounds__(256) void ln_kernel(
    const float* __restrict__ x, const float* __restrict__ ln,
    float* __restrict__ out)
{
    const int row = blockIdx.x, tid = threadIdx.x;
    const float* xr = x + (size_t)row * Hc;
    float v[4], s = 0.f;
    #pragma unroll
    for (int i = 0; i < 4; i++) { v[i] = xr[tid + 256 * i]; s += v[i]; }
    s = block_sum_256(s);
    const float mean = s * (1.f / Hc);
    float q = 0.f;
    #pragma unroll
    for (int i = 0; i < 4; i++) { float d = v[i] - mean; q += d * d; }
    q = block_sum_256(q);
    const float inv = rsqrtf(q * (1.f / Hc) + LN_EPS);
    #pragma unroll
    for (int i = 0; i < 4; i++) {
        int c = tid + 256 * i;
        out[(size_t)row * Hc + c] = (v[i] - mean) * inv * ln[c] + ln[Hc + c];
    }
}

// ---------------------------------------------------------------------------
// Orchestration
// ---------------------------------------------------------------------------
extern "C" void kernel_launch(void* const* d_in, const int* in_sizes, int n_in,
                              void* d_out, int out_size)
{
    const float* hidden   = (const float*)d_in[0];
    const float* enc      = (const float*)d_in[1];
    const int*   amask    = (const int*)d_in[2];
    const int*   emask    = (const int*)d_in[3];
    const float* sa_qkv_w = (const float*)d_in[4];
    const float* sa_qkv_b = (const float*)d_in[5];
    const float* sa_out_w = (const float*)d_in[6];
    const float* sa_out_b = (const float*)d_in[7];
    const float* sa_ln    = (const float*)d_in[8];
    const float* ca_qkv_w = (const float*)d_in[9];
    const float* ca_qkv_b = (const float*)d_in[10];
    const float* ca_out_w = (const float*)d_in[11];
    const float* ca_out_b = (const float*)d_in[12];
    const float* ca_ln    = (const float*)d_in[13];
    const float* o1_w     = (const float*)d_in[14];
    const float* o1_b     = (const float*)d_in[15];
    const float* o1_ln    = (const float*)d_in[16];
    const float* ffn_w    = (const float*)d_in[17];
    const float* ffn_b    = (const float*)d_in[18];
    const float* o2_w     = (const float*)d_in[19];
    const float* o2_b     = (const float*)d_in[20];
    const float* o2_ln    = (const float*)d_in[21];
    float* out = (float*)d_out;

    static int attr_done = 0;
    if (!attr_done) {
        cudaFuncSetAttribute(gemm_tc, cudaFuncAttributeMaxDynamicSharedMemorySize, GEMM_SMEM);
        cudaFuncSetAttribute(attn_tc, cudaFuncAttributeMaxDynamicSharedMemorySize, ATTN_SMEM);
        attr_done = 1;
    }

    float *h, *q, *k, *v, *a, *t, *x1, *x2, *x3, *inter;
    cudaGetSymbolAddress((void**)&h,  g_h);
    cudaGetSymbolAddress((void**)&q,  g_q);
    cudaGetSymbolAddress((void**)&k,  g_k);
    cudaGetSymbolAddress((void**)&v,  g_v);
    cudaGetSymbolAddress((void**)&a,  g_a);
    cudaGetSymbolAddress((void**)&t,  g_t);
    cudaGetSymbolAddress((void**)&x1, g_x1);
    cudaGetSymbolAddress((void**)&x2, g_x2);
    cudaGetSymbolAddress((void**)&x3, g_x3);
    cudaGetSymbolAddress((void**)&inter, g_inter);

    cudaMemcpyAsync(h, hidden, (size_t)Mrows * Hc * sizeof(float),
                    cudaMemcpyDeviceToDevice, 0);

    const dim3 g1(Hc / GBN, Mrows / GBM);
    const dim3 gF(Fc / GBN, Mrows / GBM);
    const int attnBlocks = Bc * NHc * (Sc / 128);

    for (int i = 0; i < LAYERS; i++) {
        const float* W  = sa_qkv_w + (size_t)i * 3 * Hc * Hc;
        const float* Bb = sa_qkv_b + (size_t)i * 3 * Hc;
        gemm_tc<<<g1, 256, GEMM_SMEM>>>(h, W,               Bb,          nullptr, q, Mrows, Hc, Hc, 0);
        gemm_tc<<<g1, 256, GEMM_SMEM>>>(h, W + Hc * Hc,     Bb + Hc,     nullptr, k, Mrows, Hc, Hc, 0);
        gemm_tc<<<g1, 256, GEMM_SMEM>>>(h, W + 2 * Hc * Hc, Bb + 2 * Hc, nullptr, v, Mrows, Hc, Hc, 0);
        attn_tc<<<attnBlocks, 256, ATTN_SMEM>>>(q, k, v, amask, a);
        gemm_tc<<<g1, 256, GEMM_SMEM>>>(a, sa_out_w + (size_t)i * Hc * Hc, sa_out_b + i * Hc, h, t,
                                        Mrows, Hc, Hc, 0);
        ln_kernel<<<Mrows, 256>>>(t, sa_ln + (size_t)i * 2 * Hc, x1);

        const float* Wc  = ca_qkv_w + (size_t)i * 3 * Hc * Hc;
        const float* Bbc = ca_qkv_b + (size_t)i * 3 * Hc;
        gemm_tc<<<g1, 256, GEMM_SMEM>>>(h,   Wc,               Bbc,          nullptr, q, Mrows, Hc, Hc, 0);
        gemm_tc<<<g1, 256, GEMM_SMEM>>>(enc, Wc + Hc * Hc,     Bbc + Hc,     nullptr, k, Mrows, Hc, Hc, 0);
        gemm_tc<<<g1, 256, GEMM_SMEM>>>(enc, Wc + 2 * Hc * Hc, Bbc + 2 * Hc, nullptr, v, Mrows, Hc, Hc, 0);
        attn_tc<<<attnBlocks, 256, ATTN_SMEM>>>(q, k, v, emask, a);
        gemm_tc<<<g1, 256, GEMM_SMEM>>>(a, ca_out_w + (size_t)i * Hc * Hc, ca_out_b + i * Hc, h, t,
                                        Mrows, Hc, Hc, 0);
        ln_kernel<<<Mrows, 256>>>(t, ca_ln + (size_t)i * 2 * Hc, x2);

        gemm_tc<<<g1, 256, GEMM_SMEM>>>(x1, o1_w + (size_t)i * Hc * Hc, o1_b + i * Hc, x2, t,
                                        Mrows, Hc, Hc, 0);
        ln_kernel<<<Mrows, 256>>>(t, o1_ln + (size_t)i * 2 * Hc, x3);

        gemm_tc<<<gF, 256, GEMM_SMEM>>>(x3, ffn_w + (size_t)i * Hc * Fc, ffn_b + (size_t)i * Fc,
                                        nullptr, inter, Mrows, Fc, Hc, 1);
        gemm_tc<<<g1, 256, GEMM_SMEM>>>(inter, o2_w + (size_t)i * Fc * Hc, o2_b + i * Hc, x3, t,
                                        Mrows, Hc, Fc, 0);
        ln_kernel<<<Mrows, 256>>>(t, o2_ln + (size_t)i * 2 * Hc,
                                  (i == LAYERS - 1) ? out : h);
    }
}

// round 11
// speedup vs baseline: 4.2016x; 1.7349x over previous
#include <cuda_runtime.h>
#include <cuda_bf16.h>
#include <math.h>

#define LAYERS 6
#define Hc 1024
#define NHc 16
#define Dc 64
#define Fc 4096
#define Bc 4
#define Sc 512
#define Mrows (Bc * Sc)
#define LN_EPS 1e-12f
#define GELU_C 0.7978845608028654f

__device__ float g_h[Mrows * Hc];
__device__ float g_q[Mrows * Hc];
__device__ float g_k[Mrows * Hc];
__device__ float g_v[Mrows * Hc];
__device__ float g_a[Mrows * Hc];
__device__ float g_t[Mrows * Hc];
__device__ float g_x1[Mrows * Hc];
__device__ float g_x2[Mrows * Hc];
__device__ float g_x3[Mrows * Hc];
__device__ float g_inter[Mrows * Fc];

// ---- bf16 hi/lo split helpers: x = hi + lo with |lo| <= 2^-9|x|, packed as
// bf16x2 words holding (even k in low half, odd k in high half). ----
__device__ __forceinline__ void bfsplit2(float x0, float x1, unsigned& hi, unsigned& lo) {
    unsigned h;
    asm("cvt.rn.bf16x2.f32 %0, %1, %2;" : "=r"(h) : "f"(x1), "f"(x0)); // hi16=x1, lo16=x0
    float h0 = __uint_as_float(h << 16);
    float h1 = __uint_as_float(h & 0xffff0000u);
    unsigned l;
    asm("cvt.rn.bf16x2.f32 %0, %1, %2;" : "=r"(l) : "f"(x1 - h1), "f"(x0 - h0));
    hi = h; lo = l;
}
// m16n8k16 bf16 MMA: 4 A-regs (bf16x2), 2 B-regs, 4 f32 acc.
__device__ __forceinline__ void mma16(float* c, const unsigned* a, const unsigned* b) {
    asm("mma.sync.aligned.m16n8k16.row.col.f32.bf16.bf16.f32 "
        "{%0,%1,%2,%3}, {%4,%5,%6,%7}, {%8,%9}, {%0,%1,%2,%3};"
        : "+f"(c[0]), "+f"(c[1]), "+f"(c[2]), "+f"(c[3])
        : "r"(a[0]), "r"(a[1]), "r"(a[2]), "r"(a[3]), "r"(b[0]), "r"(b[1]));
}
__device__ __forceinline__ float gelu_new(float x) {
    return 0.5f * x * (1.0f + tanhf(GELU_C * (x + 0.044715f * x * x * x)));
}

// ---------------------------------------------------------------------------
// GEMM (bf16x2 split): C = A@W + bias (+add) (+gelu). 128x128x16 tiles,
// 8 warps (2x4), 64x32 warp tiles, double-buffered. Smem holds bf16x2 pairs:
// A/B as [kpair 8][128] per buffer.
// ---------------------------------------------------------------------------
#define GBM 128
#define GBN 128
#define GBK 16
#define LDA 136    // ≡8 mod 32: frag reads 8*tg+g conflict-free
#define LDB 136
#define GEMM_SMEM (4 * 2 * 8 * LDA * 4)   // 34816 B

__global__ __launch_bounds__(256) void gemm_tc(
    const float* __restrict__ A, const float* __restrict__ W,
    const float* __restrict__ bias, const float* __restrict__ add,
    float* __restrict__ C, int M, int N, int K, int fuse_gelu)
{
    extern __shared__ unsigned sm_g[];
    unsigned* Ah = sm_g;
    unsigned* Al = Ah + 2 * 8 * LDA;
    unsigned* Bh = Al + 2 * 8 * LDA;
    unsigned* Bl = Bh + 2 * 8 * LDB;

    const int tid = threadIdx.x, lane = tid & 31, warp = tid >> 5;
    const int wr = warp >> 2, wc = warp & 3;
    const int g = lane >> 2, tg = lane & 3;
    const int bm = blockIdx.y * GBM, bn = blockIdx.x * GBN;
    const int am = tid >> 1, ak = (tid & 1) * 8;        // A: row am, k ak..ak+7
    const int kp = tid >> 5, col0 = (tid & 31) * 4;     // B: rows 2kp,2kp+1, 4 cols

    float acc[4][4][4];
    #pragma unroll
    for (int i = 0; i < 4; i++)
        #pragma unroll
        for (int j = 0; j < 4; j++)
            #pragma unroll
            for (int r = 0; r < 4; r++) acc[i][j][r] = 0.f;

    float ar[8], br[8];
    const float* Abase = A + (size_t)(bm + am) * K + ak;
    const float* Wbase = W + (size_t)(2 * kp) * N + bn + col0;

    auto loadT = [&](int t) {
        const float4* pa = (const float4*)(Abase + t * GBK);
        float4 u = pa[0], v2 = pa[1];
        ar[0] = u.x; ar[1] = u.y; ar[2] = u.z; ar[3] = u.w;
        ar[4] = v2.x; ar[5] = v2.y; ar[6] = v2.z; ar[7] = v2.w;
        const float* p0 = Wbase + (size_t)t * GBK * N;
        float4 x = *(const float4*)p0;
        float4 y = *(const float4*)(p0 + N);
        br[0] = x.x; br[1] = x.y; br[2] = x.z; br[3] = x.w;
        br[4] = y.x; br[5] = y.y; br[6] = y.z; br[7] = y.w;
    };
    auto storeT = [&](int buf) {
        #pragma unroll
        for (int i = 0; i < 4; i++) {
            unsigned h, l;
            bfsplit2(ar[2 * i], ar[2 * i + 1], h, l);       // pairs along k
            Ah[(buf * 8 + (ak >> 1) + i) * LDA + am] = h;
            Al[(buf * 8 + (ak >> 1) + i) * LDA + am] = l;
        }
        unsigned bh4[4], bl4[4];
        #pragma unroll
        for (int j = 0; j < 4; j++) bfsplit2(br[j], br[4 + j], bh4[j], bl4[j]);
        *(uint4*)&Bh[(buf * 8 + kp) * LDB + col0] = make_uint4(bh4[0], bh4[1], bh4[2], bh4[3]);
        *(uint4*)&Bl[(buf * 8 + kp) * LDB + col0] = make_uint4(bl4[0], bl4[1], bl4[2], bl4[3]);
    };
    auto compute = [&](int buf) {
        const int r0 = (buf * 8 + tg) * LDA, r1 = (buf * 8 + tg + 4) * LDA;
        unsigned ah[4][4], al_[4][4];
        #pragma unroll
        for (int i = 0; i < 4; i++) {
            int rb = wr * 64 + i * 16 + g;
            ah[i][0] = Ah[r0 + rb];   ah[i][1] = Ah[r0 + rb + 8];
            ah[i][2] = Ah[r1 + rb];   ah[i][3] = Ah[r1 + rb + 8];
            al_[i][0] = Al[r0 + rb];  al_[i][1] = Al[r0 + rb + 8];
            al_[i][2] = Al[r1 + rb];  al_[i][3] = Al[r1 + rb + 8];
        }
        const int s0 = (buf * 8 + tg) * LDB, s1 = (buf * 8 + tg + 4) * LDB;
        #pragma unroll
        for (int j = 0; j < 4; j++) {
            int cb = wc * 32 + j * 8 + g;
            unsigned bh2[2], bl2[2];
            bh2[0] = Bh[s0 + cb]; bh2[1] = Bh[s1 + cb];
            bl2[0] = Bl[s0 + cb]; bl2[1] = Bl[s1 + cb];
            #pragma unroll
            for (int i = 0; i < 4; i++) {
                mma16(acc[i][j], ah[i], bh2);
                mma16(acc[i][j], ah[i], bl2);
                mma16(acc[i][j], al_[i], bh2);
            }
        }
    };

    const int T = K / GBK;
    loadT(0); storeT(0); __syncthreads();
    for (int t = 0; t < T; t++) {
        int cur = t & 1;
        if (t + 1 < T) loadT(t + 1);
        compute(cur);
        if (t + 1 < T) storeT(cur ^ 1);
        __syncthreads();
    }

    #pragma unroll
    for (int i = 0; i < 4; i++) {
        int row0 = bm + wr * 64 + i * 16 + g;
        #pragma unroll
        for (int j = 0; j < 4; j++) {
            int col = bn + wc * 32 + j * 8 + 2 * tg;
            float2 bz = *(const float2*)(bias + col);
            float v0 = acc[i][j][0] + bz.x, v1 = acc[i][j][1] + bz.y;
            float v2 = acc[i][j][2] + bz.x, v3 = acc[i][j][3] + bz.y;
            if (add) {
                float2 a0 = *(const float2*)(add + (size_t)row0 * N + col);
                float2 a1 = *(const float2*)(add + (size_t)(row0 + 8) * N + col);
                v0 += a0.x; v1 += a0.y; v2 += a1.x; v3 += a1.y;
            }
            if (fuse_gelu) {
                v0 = gelu_new(v0); v1 = gelu_new(v1);
                v2 = gelu_new(v2); v3 = gelu_new(v3);
            }
            *(float2*)(C + (size_t)row0 * N + col) = make_float2(v0, v1);
            *(float2*)(C + (size_t)(row0 + 8) * N + col) = make_float2(v2, v3);
        }
    }
}

// ---------------------------------------------------------------------------
// FlashAttention (bf16x2 split, m16n8k16). 128 q rows per block, 8 warps x 16
// rows, kv tiles of 64, online softmax. S-acc frag reused directly as P A-frag.
// Layouts: Q [row][dpair] LDQ=36 (≡4 mod 32); K [dpair][kv] LDK=72 (≡8);
//          V [kvpair][d] LDV=72.
// ---------------------------------------------------------------------------
#define LDQ 36
#define LDK 72
#define LDV 72
#define ATTN_SMEM ((2 * 128 * LDQ + 2 * 32 * LDK + 2 * 32 * LDV) * 4 + Sc * 4)

__global__ __launch_bounds__(256) void attn_tc(
    const float* __restrict__ Q, const float* __restrict__ Kin,
    const float* __restrict__ Vin, const int* __restrict__ mask,
    float* __restrict__ O)
{
    extern __shared__ unsigned sm_a[];
    unsigned* Qh = sm_a;
    unsigned* Ql = Qh + 128 * LDQ;
    unsigned* Kh = Ql + 128 * LDQ;
    unsigned* Kl = Kh + 32 * LDK;
    unsigned* Vh = Kl + 32 * LDK;
    unsigned* Vl = Vh + 32 * LDV;
    float* madd = (float*)(Vl + 32 * LDV);

    const int tid = threadIdx.x, lane = tid & 31, warp = tid >> 5;
    const int g = lane >> 2, tg = lane & 3;
    const int qt = blockIdx.x & 3;
    const int n  = (blockIdx.x >> 2) & 15;
    const int b  = blockIdx.x >> 6;

    for (int j = tid; j < Sc; j += 256)
        madd[j] = mask[b * Sc + j] ? 0.f : -10000.f;

    {   // Q tile [128][64] -> [row][dpair]
        int r = tid >> 1, d0 = (tid & 1) * 32;
        const float* qp = Q + (size_t)(b * Sc + qt * 128 + r) * Hc + n * Dc + d0;
        #pragma unroll
        for (int i = 0; i < 32; i += 8) {
            float4 u = *(const float4*)(qp + i);
            float4 w = *(const float4*)(qp + i + 4);
            unsigned h0, l0, h1, l1, h2, l2, h3, l3;
            bfsplit2(u.x, u.y, h0, l0); bfsplit2(u.z, u.w, h1, l1);
            bfsplit2(w.x, w.y, h2, l2); bfsplit2(w.z, w.w, h3, l3);
            *(uint4*)&Qh[r * LDQ + ((d0 + i) >> 1)] = make_uint4(h0, h1, h2, h3);
            *(uint4*)&Ql[r * LDQ + ((d0 + i) >> 1)] = make_uint4(l0, l1, l2, l3);
        }
    }
    __syncthreads();

    float o[8][4];
    #pragma unroll
    for (int j = 0; j < 8; j++)
        #pragma unroll
        for (int r = 0; r < 4; r++) o[j][r] = 0.f;
    float m_run[2] = {-1e30f, -1e30f};
    float l_run[2] = {0.f, 0.f};

    for (int kv = 0; kv < Sc; kv += 64) {
        {   // K tile [64 kv][64 d] -> [dpair][kv]
            int r = tid >> 2, d0 = (tid & 3) * 16;
            const float* kpp = Kin + (size_t)(b * Sc + kv + r) * Hc + n * Dc + d0;
            float4 u = *(const float4*)(kpp);
            float4 w = *(const float4*)(kpp + 4);
            float4 x = *(const float4*)(kpp + 8);
            float4 y = *(const float4*)(kpp + 12);
            float pv[16] = {u.x, u.y, u.z, u.w, w.x, w.y, w.z, w.w,
                            x.x, x.y, x.z, x.w, y.x, y.y, y.z, y.w};
            #pragma unroll
            for (int p = 0; p < 8; p++) {
                unsigned h, l;
                bfsplit2(pv[2 * p], pv[2 * p + 1], h, l);
                Kh[((d0 >> 1) + p) * LDK + r] = h;
                Kl[((d0 >> 1) + p) * LDK + r] = l;
            }
            // V tile [64 kv][64 d] -> [kvpair][d]
            int kp2 = tid >> 3, dv0 = (tid & 7) * 8;
            const float* v0p = Vin + (size_t)(b * Sc + kv + 2 * kp2) * Hc + n * Dc + dv0;
            float4 a0 = *(const float4*)(v0p);
            float4 a1 = *(const float4*)(v0p + 4);
            float4 b0 = *(const float4*)(v0p + Hc);
            float4 b1 = *(const float4*)(v0p + Hc + 4);
            unsigned hh[8], ll[8];
            bfsplit2(a0.x, b0.x, hh[0], ll[0]); bfsplit2(a0.y, b0.y, hh[1], ll[1]);
            bfsplit2(a0.z, b0.z, hh[2], ll[2]); bfsplit2(a0.w, b0.w, hh[3], ll[3]);
            bfsplit2(a1.x, b1.x, hh[4], ll[4]); bfsplit2(a1.y, b1.y, hh[5], ll[5]);
            bfsplit2(a1.z, b1.z, hh[6], ll[6]); bfsplit2(a1.w, b1.w, hh[7], ll[7]);
            *(uint4*)&Vh[kp2 * LDV + dv0]     = make_uint4(hh[0], hh[1], hh[2], hh[3]);
            *(uint4*)&Vh[kp2 * LDV + dv0 + 4] = make_uint4(hh[4], hh[5], hh[6], hh[7]);
            *(uint4*)&Vl[kp2 * LDV + dv0]     = make_uint4(ll[0], ll[1], ll[2], ll[3]);
            *(uint4*)&Vl[kp2 * LDV + dv0 + 4] = make_uint4(ll[4], ll[5], ll[6], ll[7]);
        }
        __syncthreads();

        // S = Q K^T (4 k16 steps over d=64)
        float s[8][4];
        #pragma unroll
        for (int j = 0; j < 8; j++)
            #pragma unroll
            for (int r = 0; r < 4; r++) s[j][r] = 0.f;
        #pragma unroll
        for (int kk2 = 0; kk2 < 32; kk2 += 8) {
            int rb = warp * 16 + g;
            unsigned qh[4], ql_[4];
            qh[0] = Qh[rb * LDQ + kk2 + tg];        qh[1] = Qh[(rb + 8) * LDQ + kk2 + tg];
            qh[2] = Qh[rb * LDQ + kk2 + tg + 4];    qh[3] = Qh[(rb + 8) * LDQ + kk2 + tg + 4];
            ql_[0] = Ql[rb * LDQ + kk2 + tg];       ql_[1] = Ql[(rb + 8) * LDQ + kk2 + tg];
            ql_[2] = Ql[rb * LDQ + kk2 + tg + 4];   ql_[3] = Ql[(rb + 8) * LDQ + kk2 + tg + 4];
            #pragma unroll
            for (int j = 0; j < 8; j++) {
                unsigned kh2[2], kl2[2];
                kh2[0] = Kh[(kk2 + tg) * LDK + j * 8 + g];
                kh2[1] = Kh[(kk2 + tg + 4) * LDK + j * 8 + g];
                kl2[0] = Kl[(kk2 + tg) * LDK + j * 8 + g];
                kl2[1] = Kl[(kk2 + tg + 4) * LDK + j * 8 + g];
                mma16(s[j], qh, kh2);
                mma16(s[j], qh, kl2);
                mma16(s[j], ql_, kh2);
            }
        }

        // Online softmax
        float corr[2];
        #pragma unroll
        for (int r2 = 0; r2 < 2; r2++) {
            float mx = m_run[r2];
            #pragma unroll
            for (int j = 0; j < 8; j++)
                #pragma unroll
                for (int c = 0; c < 2; c++) {
                    float val = s[j][r2 * 2 + c] * 0.125f + madd[kv + j * 8 + 2 * tg + c];
                    s[j][r2 * 2 + c] = val;
                    mx = fmaxf(mx, val);
                }
            mx = fmaxf(mx, __shfl_xor_sync(0xffffffffu, mx, 1));
            mx = fmaxf(mx, __shfl_xor_sync(0xffffffffu, mx, 2));
            corr[r2] = __expf(m_run[r2] - mx);
            m_run[r2] = mx;
            float rs = 0.f;
            #pragma unroll
            for (int j = 0; j < 8; j++)
                #pragma unroll
                for (int c = 0; c < 2; c++) {
                    float e = __expf(s[j][r2 * 2 + c] - mx);
                    s[j][r2 * 2 + c] = e;
                    rs += e;
                }
            rs += __shfl_xor_sync(0xffffffffu, rs, 1);
            rs += __shfl_xor_sync(0xffffffffu, rs, 2);
            l_run[r2] = l_run[r2] * corr[r2] + rs;
        }
        #pragma unroll
        for (int j = 0; j < 8; j++) {
            o[j][0] *= corr[0]; o[j][1] *= corr[0];
            o[j][2] *= corr[1]; o[j][3] *= corr[1];
        }

        // O += P V: S-acc frag packs directly into the k16 A-frag (no shuffles)
        #pragma unroll
        for (int kf = 0; kf < 4; kf++) {
            unsigned ph[4], pl[4];
            bfsplit2(s[2 * kf][0],     s[2 * kf][1],     ph[0], pl[0]);
            bfsplit2(s[2 * kf][2],     s[2 * kf][3],     ph[1], pl[1]);
            bfsplit2(s[2 * kf + 1][0], s[2 * kf + 1][1], ph[2], pl[2]);
            bfsplit2(s[2 * kf + 1][2], s[2 * kf + 1][3], ph[3], pl[3]);
            #pragma unroll
            for (int j = 0; j < 8; j++) {
                unsigned vh2[2], vl2[2];
                vh2[0] = Vh[(kf * 8 + tg) * LDV + j * 8 + g];
                vh2[1] = Vh[(kf * 8 + tg + 4) * LDV + j * 8 + g];
                vl2[0] = Vl[(kf * 8 + tg) * LDV + j * 8 + g];
                vl2[1] = Vl[(kf * 8 + tg + 4) * LDV + j * 8 + g];
                mma16(o[j], ph, vh2);
                mma16(o[j], ph, vl2);
                mma16(o[j], pl, vh2);
            }
        }
        __syncthreads();
    }

    float inv0 = 1.f / l_run[0], inv1 = 1.f / l_run[1];
    int row0 = b * Sc + qt * 128 + warp * 16 + g;
    #pragma unroll
    for (int j = 0; j < 8; j++) {
        int col = n * Dc + j * 8 + 2 * tg;
        *(float2*)(O + (size_t)row0 * Hc + col) =
            make_float2(o[j][0] * inv0, o[j][1] * inv0);
        *(float2*)(O + (size_t)(row0 + 8) * Hc + col) =
            make_float2(o[j][2] * inv1, o[j][3] * inv1);
    }
}

// ---------------------------------------------------------------------------
// LayerNorm over H=1024
// ---------------------------------------------------------------------------
__device__ __forceinline__ float block_sum_256(float v) {
    __shared__ float sh[8];
    #pragma unroll
    for (int o = 16; o > 0; o >>= 1) v += __shfl_xor_sync(0xffffffffu, v, o);
    __syncthreads();
    if ((threadIdx.x & 31) == 0) sh[threadIdx.x >> 5] = v;
    __syncthreads();
    float t = sh[0];
    #pragma unroll
    for (int i = 1; i < 8; i++) t += sh[i];
    return t;
}

__global__ __launch_bounds__(256) void ln_kernel(
    const float* __restrict__ x, const float* __restrict__ ln,
    float* __restrict__ out)
{
    const int row = blockIdx.x, tid = threadIdx.x;
    const float* xr = x + (size_t)row * Hc;
    float v[4], s = 0.f;
    #pragma unroll
    for (int i = 0; i < 4; i++) { v[i] = xr[tid + 256 * i]; s += v[i]; }
    s = block_sum_256(s);
    const float mean = s * (1.f / Hc);
    float q = 0.f;
    #pragma unroll
    for (int i = 0; i < 4; i++) { float d = v[i] - mean; q += d * d; }
    q = block_sum_256(q);
    const float inv = rsqrtf(q * (1.f / Hc) + LN_EPS);
    #pragma unroll
    for (int i = 0; i < 4; i++) {
        int c = tid + 256 * i;
        out[(size_t)row * Hc + c] = (v[i] - mean) * inv * ln[c] + ln[Hc + c];
    }
}

// ---------------------------------------------------------------------------
// Orchestration
// ---------------------------------------------------------------------------
extern "C" void kernel_launch(void* const* d_in, const int* in_sizes, int n_in,
                              void* d_out, int out_size)
{
    const float* hidden   = (const float*)d_in[0];
    const float* enc      = (const float*)d_in[1];
    const int*   amask    = (const int*)d_in[2];
    const int*   emask    = (const int*)d_in[3];
    const float* sa_qkv_w = (const float*)d_in[4];
    const float* sa_qkv_b = (const float*)d_in[5];
    const float* sa_out_w = (const float*)d_in[6];
    const float* sa_out_b = (const float*)d_in[7];
    const float* sa_ln    = (const float*)d_in[8];
    const float* ca_qkv_w = (const float*)d_in[9];
    const float* ca_qkv_b = (const float*)d_in[10];
    const float* ca_out_w = (const float*)d_in[11];
    const float* ca_out_b = (const float*)d_in[12];
    const float* ca_ln    = (const float*)d_in[13];
    const float* o1_w     = (const float*)d_in[14];
    const float* o1_b     = (const float*)d_in[15];
    const float* o1_ln    = (const float*)d_in[16];
    const float* ffn_w    = (const float*)d_in[17];
    const float* ffn_b    = (const float*)d_in[18];
    const float* o2_w     = (const float*)d_in[19];
    const float* o2_b     = (const float*)d_in[20];
    const float* o2_ln    = (const float*)d_in[21];
    float* out = (float*)d_out;

    cudaFuncSetAttribute(gemm_tc, cudaFuncAttributeMaxDynamicSharedMemorySize, GEMM_SMEM);
    cudaFuncSetAttribute(attn_tc, cudaFuncAttributeMaxDynamicSharedMemorySize, ATTN_SMEM);

    float *h, *q, *k, *v, *a, *t, *x1, *x2, *x3, *inter;
    cudaGetSymbolAddress((void**)&h,  g_h);
    cudaGetSymbolAddress((void**)&q,  g_q);
    cudaGetSymbolAddress((void**)&k,  g_k);
    cudaGetSymbolAddress((void**)&v,  g_v);
    cudaGetSymbolAddress((void**)&a,  g_a);
    cudaGetSymbolAddress((void**)&t,  g_t);
    cudaGetSymbolAddress((void**)&x1, g_x1);
    cudaGetSymbolAddress((void**)&x2, g_x2);
    cudaGetSymbolAddress((void**)&x3, g_x3);
    cudaGetSymbolAddress((void**)&inter, g_inter);

    cudaMemcpyAsync(h, hidden, (size_t)Mrows * Hc * sizeof(float),
                    cudaMemcpyDeviceToDevice, 0);

    const dim3 g1(Hc / GBN, Mrows / GBM);
    const dim3 gF(Fc / GBN, Mrows / GBM);
    const int attnBlocks = Bc * NHc * (Sc / 128);

    for (int i = 0; i < LAYERS; i++) {
        const float* W  = sa_qkv_w + (size_t)i * 3 * Hc * Hc;
        const float* Bb = sa_qkv_b + (size_t)i * 3 * Hc;
        gemm_tc<<<g1, 256, GEMM_SMEM>>>(h, W,               Bb,          nullptr, q, Mrows, Hc, Hc, 0);
        gemm_tc<<<g1, 256, GEMM_SMEM>>>(h, W + Hc * Hc,     Bb + Hc,     nullptr, k, Mrows, Hc, Hc, 0);
        gemm_tc<<<g1, 256, GEMM_SMEM>>>(h, W + 2 * Hc * Hc, Bb + 2 * Hc, nullptr, v, Mrows, Hc, Hc, 0);
        attn_tc<<<attnBlocks, 256, ATTN_SMEM>>>(q, k, v, amask, a);
        gemm_tc<<<g1, 256, GEMM_SMEM>>>(a, sa_out_w + (size_t)i * Hc * Hc, sa_out_b + i * Hc, h, t,
                                        Mrows, Hc, Hc, 0);
        ln_kernel<<<Mrows, 256>>>(t, sa_ln + (size_t)i * 2 * Hc, x1);

        const float* Wc  = ca_qkv_w + (size_t)i * 3 * Hc * Hc;
        const float* Bbc = ca_qkv_b + (size_t)i * 3 * Hc;
        gemm_tc<<<g1, 256, GEMM_SMEM>>>(h,   Wc,               Bbc,          nullptr, q, Mrows, Hc, Hc, 0);
        gemm_tc<<<g1, 256, GEMM_SMEM>>>(enc, Wc + Hc * Hc,     Bbc + Hc,     nullptr, k, Mrows, Hc, Hc, 0);
        gemm_tc<<<g1, 256, GEMM_SMEM>>>(enc, Wc + 2 * Hc * Hc, Bbc + 2 * Hc, nullptr, v, Mrows, Hc, Hc, 0);
        attn_tc<<<attnBlocks, 256, ATTN_SMEM>>>(q, k, v, emask, a);
        gemm_tc<<<g1, 256, GEMM_SMEM>>>(a, ca_out_w + (size_t)i * Hc * Hc, ca_out_b + i * Hc, h, t,
                                        Mrows, Hc, Hc, 0);
        ln_kernel<<<Mrows, 256>>>(t, ca_ln + (size_t)i * 2 * Hc, x2);

        gemm_tc<<<g1, 256, GEMM_SMEM>>>(x1, o1_w + (size_t)i * Hc * Hc, o1_b + i * Hc, x2, t,
                                        Mrows, Hc, Hc, 0);
        ln_kernel<<<Mrows, 256>>>(t, o1_ln + (size_t)i * 2 * Hc, x3);

        gemm_tc<<<gF, 256, GEMM_SMEM>>>(x3, ffn_w + (size_t)i * Hc * Fc, ffn_b + (size_t)i * Fc,
                                        nullptr, inter, Mrows, Fc, Hc, 1);
        gemm_tc<<<g1, 256, GEMM_SMEM>>>(inter, o2_w + (size_t)i * Fc * Hc, o2_b + i * Hc, x3, t,
                                        Mrows, Hc, Fc, 0);
        ln_kernel<<<Mrows, 256>>>(t, o2_ln + (size_t)i * 2 * Hc,
                                  (i == LAYERS - 1) ? out : h);
    }
}